// round 2
// baseline (speedup 1.0000x reference)
#include <cuda_runtime.h>
#include <cuda_bf16.h>

#define NPTS 250000
#define BATCH 2
#define CCH 64
#define PPB 64         // points per block in main kernel
#define MTHREADS 128

// scratch: z-mean sums [sumz_b0, cnt_b0, sumz_b1, cnt_b1]
__device__ float g_zsum[2 * BATCH];
// folded weights: W1f [0,640), t1 [640,704), W2f [704,4800), t2 [4800,4864)
__device__ float g_fold[10 * CCH + CCH + CCH * CCH + CCH];

// ---------------------------------------------------------------------------
// Fold BatchNorm into the linear weights:
//   h = relu((aug.W1 - m1)*s1 + b1) = relu(aug.(W1*s1) + (b1 - m1*s1))
// ---------------------------------------------------------------------------
__global__ void prep_kernel(const float* __restrict__ W1, const float* __restrict__ g1,
                            const float* __restrict__ b1, const float* __restrict__ m1,
                            const float* __restrict__ v1,
                            const float* __restrict__ W2, const float* __restrict__ g2,
                            const float* __restrict__ b2, const float* __restrict__ m2,
                            const float* __restrict__ v2) {
    int c = threadIdx.x;
    if (c >= CCH) return;
    float s1 = g1[c] * rsqrtf(v1[c] + 1e-5f);
    float s2 = g2[c] * rsqrtf(v2[c] + 1e-5f);
    g_fold[640 + c]  = b1[c] - m1[c] * s1;
    g_fold[4800 + c] = b2[c] - m2[c] * s2;
#pragma unroll
    for (int f = 0; f < 10; f++) g_fold[f * 64 + c] = W1[f * 64 + c] * s1;
    for (int k = 0; k < 64; k++) g_fold[704 + k * 64 + c] = W2[k * 64 + c] * s2;
}

// ---------------------------------------------------------------------------
// z_mean reduction: sum(z*mask), sum(mask) per batch.  mask is int32.
// ---------------------------------------------------------------------------
__global__ void zmean_kernel(const float* __restrict__ points,
                             const int* __restrict__ mask) {
    int b = blockIdx.y;
    float s = 0.f, cnt = 0.f;
    for (int i = blockIdx.x * blockDim.x + threadIdx.x; i < NPTS;
         i += gridDim.x * blockDim.x) {
        float m = mask[(size_t)b * NPTS + i] ? 1.f : 0.f;
        float z = points[((size_t)b * NPTS + i) * 5 + 2];
        s += z * m;
        cnt += m;
    }
#pragma unroll
    for (int o = 16; o; o >>= 1) {
        s   += __shfl_xor_sync(0xFFFFFFFFu, s, o);
        cnt += __shfl_xor_sync(0xFFFFFFFFu, cnt, o);
    }
    __shared__ float ss[8], sc[8];
    int w = threadIdx.x >> 5, l = threadIdx.x & 31;
    if (l == 0) { ss[w] = s; sc[w] = cnt; }
    __syncthreads();
    if (threadIdx.x == 0) {
        float S = 0.f, C2 = 0.f;
        int nw = (blockDim.x + 31) >> 5;
        for (int i = 0; i < nw; i++) { S += ss[i]; C2 += sc[i]; }
        atomicAdd(&g_zsum[2 * b], S);
        atomicAdd(&g_zsum[2 * b + 1], C2);
    }
}

// ---------------------------------------------------------------------------
// Main fused PFN + scatter-max kernel.
// Block: 128 threads, 64 points.
//  Phase A: threads 0..63 each compute one point's layer-1 output (64ch),
//           store transposed to shared h1s[k][p].
//  Phase B: 2D register tile — thread = (chg 0..7) x (ptg 0..15),
//           computes 4 points x 8 channels of layer-2, then REDG.MAX to out.
// ---------------------------------------------------------------------------
__global__ __launch_bounds__(MTHREADS)
void pfe_kernel(const float* __restrict__ points,
                const int* __restrict__ mask,
                float* __restrict__ out) {
    __shared__ __align__(16) float W1s[640];
    __shared__ float t1s[64];
    __shared__ __align__(16) float W2s[4096];
    __shared__ float t2s[64];
    __shared__ __align__(16) float h1s[64 * 68];   // [k][p], stride 68 (16B-aligned rows)
    __shared__ int sidx[PPB];
    __shared__ int smask[PPB];

    const int tid = threadIdx.x;
    const int b = blockIdx.y;
    const int p0 = blockIdx.x * PPB;

    // stage folded weights (L2 hits after first wave)
    for (int i = tid; i < 640; i += MTHREADS) W1s[i] = g_fold[i];
    for (int i = tid; i < 4096; i += MTHREADS) W2s[i] = g_fold[704 + i];
    if (tid < 64) { t1s[tid] = g_fold[640 + tid]; t2s[tid] = g_fold[4800 + tid]; }
    const float zm = g_zsum[2 * b] / fmaxf(g_zsum[2 * b + 1], 1.0f);
    __syncthreads();

    // ---------------- Phase A ----------------
    if (tid < PPB) {
        const int p = tid;
        const int gi = p0 + p;
        float aug[10];
        if (gi < NPTS) {
            const size_t base = ((size_t)b * NPTS + gi) * 5;
            const float x = points[base + 0];
            const float y = points[base + 1];
            const float z = points[base + 2];
            const float it = points[base + 3];
            const float rg = points[base + 4];
            // replicate reference binning exactly: (x - PCR)/VS with RN division
            const float fx = __fdiv_rn(x - (-51.2f), 0.1f);
            const float fy = __fdiv_rn(y - (-51.2f), 0.1f);
            int px = (int)floorf(fx);
            int py = (int)floorf(fy);
            px = min(max(px, 0), 1023);
            py = min(max(py, 0), 1023);
            const float pxf = (float)px, pyf = (float)py;
            aug[0] = x; aug[1] = y; aug[2] = z; aug[3] = it; aug[4] = rg;
            aug[5] = x - (pxf * 0.1f + (-51.2f) + 0.05f);
            aug[6] = y - (pyf * 0.1f + (-51.2f) + 0.05f);
            aug[7] = z - zm;
            aug[8] = x - (pxf * 0.1f + (-51.2f));
            aug[9] = y - (pyf * 0.1f + (-51.2f));
            sidx[p] = py * 1024 + px;
            smask[p] = mask[(size_t)b * NPTS + gi] != 0;
        } else {
            sidx[p] = 0;
            smask[p] = 0;
#pragma unroll
            for (int f = 0; f < 10; f++) aug[f] = 0.f;
        }
        float h1a[64];
#pragma unroll
        for (int c = 0; c < 64; c++) h1a[c] = t1s[c];
#pragma unroll
        for (int f = 0; f < 10; f++) {
            const float a = aug[f];
#pragma unroll
            for (int c = 0; c < 64; c++)
                h1a[c] = fmaf(a, W1s[f * 64 + c], h1a[c]);
        }
#pragma unroll
        for (int c = 0; c < 64; c++)
            h1s[c * 68 + p] = fmaxf(h1a[c], 0.f);
    }
    __syncthreads();

    // ---------------- Phase B ----------------
    const int chg = tid & 7;    // channel group: channels chg*8 .. +7
    const int ptg = tid >> 3;   // point group:   points  ptg*4 .. +3

    float acc[4][8];
#pragma unroll
    for (int i = 0; i < 4; i++)
#pragma unroll
        for (int j = 0; j < 8; j++) acc[i][j] = t2s[chg * 8 + j];

#pragma unroll 8
    for (int k = 0; k < 64; k++) {
        const float4 hv = *(const float4*)(h1s + k * 68 + ptg * 4);
        const float4 wa = *(const float4*)(W2s + k * 64 + chg * 8);
        const float4 wb = *(const float4*)(W2s + k * 64 + chg * 8 + 4);
        const float hq[4] = {hv.x, hv.y, hv.z, hv.w};
        const float wq[8] = {wa.x, wa.y, wa.z, wa.w, wb.x, wb.y, wb.z, wb.w};
#pragma unroll
        for (int i = 0; i < 4; i++)
#pragma unroll
            for (int j = 0; j < 8; j++)
                acc[i][j] = fmaf(hq[i], wq[j], acc[i][j]);
    }

    // epilogue: relu + masked scatter-max (non-negative floats compare as ints)
#pragma unroll
    for (int i = 0; i < 4; i++) {
        const int p = ptg * 4 + i;
        if (!smask[p]) continue;
        const int cell = sidx[p];
#pragma unroll
        for (int j = 0; j < 8; j++) {
            const float v = acc[i][j];
            if (v > 0.f) {
                const int c = chg * 8 + j;
                atomicMax((int*)&out[((size_t)(b * CCH + c) << 20) + (size_t)cell],
                          __float_as_int(v));
            }
        }
    }
}

// ---------------------------------------------------------------------------
extern "C" void kernel_launch(void* const* d_in, const int* in_sizes, int n_in,
                              void* d_out, int out_size) {
    const float* points = (const float*)d_in[0];
    const int* pmask    = (const int*)d_in[1];
    const float* W1 = (const float*)d_in[2];
    const float* g1 = (const float*)d_in[3];
    const float* b1 = (const float*)d_in[4];
    const float* m1 = (const float*)d_in[5];
    const float* v1 = (const float*)d_in[6];
    const float* W2 = (const float*)d_in[7];
    const float* g2 = (const float*)d_in[8];
    const float* b2 = (const float*)d_in[9];
    const float* m2 = (const float*)d_in[10];
    const float* v2 = (const float*)d_in[11];
    float* out = (float*)d_out;

    // zero the full BEV output (empty cells must be 0)
    cudaMemsetAsync(out, 0, (size_t)out_size * sizeof(float), 0);

    // zero z-mean scratch
    void* zptr = nullptr;
    cudaGetSymbolAddress(&zptr, g_zsum);
    cudaMemsetAsync(zptr, 0, sizeof(float) * 2 * BATCH, 0);

    prep_kernel<<<1, 64>>>(W1, g1, b1, m1, v1, W2, g2, b2, m2, v2);

    dim3 zg(64, BATCH);
    zmean_kernel<<<zg, 256>>>(points, pmask);

    dim3 mg((NPTS + PPB - 1) / PPB, BATCH);
    pfe_kernel<<<mg, MTHREADS>>>(points, pmask, out);
}

// round 4
// speedup vs baseline: 1.2333x; 1.2333x over previous
#include <cuda_runtime.h>

#define NPTS 250000
#define BATCH 2
#define OUT_ELEMS (BATCH * 64 * 1024 * 1024)
#define ZBLK 4096
#define ZMB 64                 // zmean blocks per batch
#define PPB 128
#define MTHREADS 128
#define SMEM_BYTES 54272       // 13568 floats

typedef unsigned long long ull;

// zmean partials: [batch][0=sum,1=cnt][block]
__device__ float g_part[BATCH][2][ZMB];
// folded weights: W1f [0,640) t1 [640,704) W2f [704,4800) t2 [4800,4864)
__device__ float g_fold[4864];

__device__ __forceinline__ ull dup2(float a) {
    ull r; asm("mov.b64 %0, {%1, %1};" : "=l"(r) : "f"(a)); return r;
}
__device__ __forceinline__ ull fma2(ull a, ull b, ull c) {
    ull d; asm("fma.rn.f32x2 %0, %1, %2, %3;" : "=l"(d) : "l"(a), "l"(b), "l"(c)); return d;
}
__device__ __forceinline__ void unpk(ull v, float& lo, float& hi) {
    asm("mov.b64 {%0, %1}, %2;" : "=f"(lo), "=f"(hi) : "l"(v));
}

// ---------------------------------------------------------------------------
// init: zero the 512MB output + zmean partials + BN fold, all in one launch.
// ---------------------------------------------------------------------------
__global__ void init_kernel(const float* __restrict__ points, const int* __restrict__ mask,
                            const float* __restrict__ W1, const float* __restrict__ g1,
                            const float* __restrict__ b1, const float* __restrict__ m1,
                            const float* __restrict__ v1,
                            const float* __restrict__ W2, const float* __restrict__ g2,
                            const float* __restrict__ b2, const float* __restrict__ m2,
                            const float* __restrict__ v2,
                            float4* __restrict__ out4) {
    const int bid = blockIdx.x, tid = threadIdx.x;

    // zero output (grid-strided, coalesced)
    const float4 z4 = make_float4(0.f, 0.f, 0.f, 0.f);
    const int total4 = OUT_ELEMS / 4;
    for (int i = bid * 256 + tid; i < total4; i += ZBLK * 256) out4[i] = z4;

    // BN fold (one block)
    if (bid == ZBLK - 1 && tid < 64) {
        const int c = tid;
        const float s1 = g1[c] * rsqrtf(v1[c] + 1e-5f);
        const float s2 = g2[c] * rsqrtf(v2[c] + 1e-5f);
        g_fold[640 + c]  = b1[c] - m1[c] * s1;
        g_fold[4800 + c] = b2[c] - m2[c] * s2;
#pragma unroll
        for (int f = 0; f < 10; f++) g_fold[f * 64 + c] = W1[f * 64 + c] * s1;
        for (int k = 0; k < 64; k++) g_fold[704 + k * 64 + c] = W2[k * 64 + c] * s2;
    }

    // zmean partials (blocks 0..127; deterministic, no atomics)
    if (bid < BATCH * ZMB) {
        const int b = bid >> 6, j = bid & 63;
        float s = 0.f, c = 0.f;
        for (int i = j * 256 + tid; i < NPTS; i += ZMB * 256) {
            if (mask[(size_t)b * NPTS + i]) {
                s += points[((size_t)b * NPTS + i) * 5 + 2];
                c += 1.f;
            }
        }
#pragma unroll
        for (int o = 16; o; o >>= 1) {
            s += __shfl_xor_sync(0xFFFFFFFFu, s, o);
            c += __shfl_xor_sync(0xFFFFFFFFu, c, o);
        }
        __shared__ float ss[8], sc[8];
        const int w = tid >> 5, l = tid & 31;
        if (l == 0) { ss[w] = s; sc[w] = c; }
        __syncthreads();
        if (tid == 0) {
            float S = 0.f, C = 0.f;
#pragma unroll
            for (int i = 0; i < 8; i++) { S += ss[i]; C += sc[i]; }
            g_part[b][0][j] = S;
            g_part[b][1][j] = C;
        }
    }
}

// ---------------------------------------------------------------------------
// Fused PFN + scatter-max.  128 threads, 128 points per block.
// Phase A: thread p computes its point's 64-ch layer-1 (f32x2 channel pairs),
//          stores transposed h1s[k][p].
// Phase B: thread = (chg 0..7) x (ptg 0..15): 8 points x 8 channels register
//          tile of layer-2 via f32x2 (channel-paired), then REDG.MAX to out.
// ---------------------------------------------------------------------------
__global__ __launch_bounds__(MTHREADS, 4)
void pfe_kernel(const float* __restrict__ points,
                const int* __restrict__ mask,
                float* __restrict__ out) {
    extern __shared__ __align__(16) float smem[];
    float* W1s = smem;                  // 640
    float* t1s = smem + 640;            // 64
    float* W2s = smem + 704;            // 4096
    float* t2s = smem + 4800;           // 64
    float* h1s = smem + 4864;           // 64 rows x stride 132
    int* sidx  = (int*)(smem + 13312);  // 128
    int* smk   = sidx + 128;            // 128
    __shared__ float zred;

    const int tid = threadIdx.x;
    const int b = blockIdx.y;
    const int p0 = blockIdx.x * PPB;

    // stage folded weights (layout of g_fold matches shared layout exactly)
    for (int i = tid; i < 4864; i += MTHREADS) smem[i] = g_fold[i];
    if (tid < 32) {
        float s = g_part[b][0][tid] + g_part[b][0][tid + 32];
        float c = g_part[b][1][tid] + g_part[b][1][tid + 32];
#pragma unroll
        for (int o = 16; o; o >>= 1) {
            s += __shfl_xor_sync(0xFFFFFFFFu, s, o);
            c += __shfl_xor_sync(0xFFFFFFFFu, c, o);
        }
        if (tid == 0) zred = s / fmaxf(c, 1.0f);
    }
    __syncthreads();
    const float zm = zred;

    // ---------------- Phase A ----------------
    {
        const int gi = p0 + tid;
        float aug[10];
        int cell = 0, mk = 0;
        if (gi < NPTS) {
            const float* pp = points + ((size_t)b * NPTS + gi) * 5;
            const float x = pp[0], y = pp[1], z = pp[2];
            aug[3] = pp[3]; aug[4] = pp[4];
            const float fx = __fdiv_rn(x - (-51.2f), 0.1f);
            const float fy = __fdiv_rn(y - (-51.2f), 0.1f);
            int px = min(max((int)floorf(fx), 0), 1023);
            int py = min(max((int)floorf(fy), 0), 1023);
            const float pxf = (float)px, pyf = (float)py;
            aug[0] = x; aug[1] = y; aug[2] = z;
            aug[5] = x - (pxf * 0.1f + (-51.2f) + 0.05f);
            aug[6] = y - (pyf * 0.1f + (-51.2f) + 0.05f);
            aug[7] = z - zm;
            aug[8] = x - (pxf * 0.1f + (-51.2f));
            aug[9] = y - (pyf * 0.1f + (-51.2f));
            cell = py * 1024 + px;
            mk = mask[(size_t)b * NPTS + gi] != 0;
        } else {
#pragma unroll
            for (int f = 0; f < 10; f++) aug[f] = 0.f;
        }
        sidx[tid] = cell;
        smk[tid] = mk;

        ull h2[32];
        const ull* t1u = (const ull*)t1s;
#pragma unroll
        for (int c2 = 0; c2 < 32; c2++) h2[c2] = t1u[c2];
        const ull* W1u = (const ull*)W1s;
#pragma unroll
        for (int f = 0; f < 10; f++) {
            const ull a = dup2(aug[f]);
#pragma unroll
            for (int c2 = 0; c2 < 32; c2++)
                h2[c2] = fma2(a, W1u[f * 32 + c2], h2[c2]);
        }
#pragma unroll
        for (int c2 = 0; c2 < 32; c2++) {
            float lo, hi; unpk(h2[c2], lo, hi);
            h1s[(2 * c2) * 132 + tid]     = fmaxf(lo, 0.f);
            h1s[(2 * c2 + 1) * 132 + tid] = fmaxf(hi, 0.f);
        }
    }
    __syncthreads();

    // ---------------- Phase B ----------------
    const int chg = tid & 7;     // channels chg*8 .. +7  (4 f32x2 pairs)
    const int ptg = tid >> 3;    // points   ptg*8 .. +7
    const float* hbase = h1s + ptg * 8;
    const ull* W2u = (const ull*)W2s;
    const ull* t2u = (const ull*)t2s;

    ull acc[8][4];
    {
        const ull t0 = t2u[chg * 4 + 0], t1v = t2u[chg * 4 + 1];
        const ull t2v = t2u[chg * 4 + 2], t3v = t2u[chg * 4 + 3];
#pragma unroll
        for (int i = 0; i < 8; i++) {
            acc[i][0] = t0; acc[i][1] = t1v; acc[i][2] = t2v; acc[i][3] = t3v;
        }
    }

#pragma unroll 4
    for (int k = 0; k < 64; k++) {
        const float4 ha = *(const float4*)(hbase + k * 132);
        const float4 hb = *(const float4*)(hbase + k * 132 + 4);
        const ull w0 = W2u[k * 32 + chg * 4 + 0];
        const ull w1 = W2u[k * 32 + chg * 4 + 1];
        const ull w2 = W2u[k * 32 + chg * 4 + 2];
        const ull w3 = W2u[k * 32 + chg * 4 + 3];
        const ull hd[8] = {dup2(ha.x), dup2(ha.y), dup2(ha.z), dup2(ha.w),
                           dup2(hb.x), dup2(hb.y), dup2(hb.z), dup2(hb.w)};
#pragma unroll
        for (int i = 0; i < 8; i++) {
            acc[i][0] = fma2(hd[i], w0, acc[i][0]);
            acc[i][1] = fma2(hd[i], w1, acc[i][1]);
            acc[i][2] = fma2(hd[i], w2, acc[i][2]);
            acc[i][3] = fma2(hd[i], w3, acc[i][3]);
        }
    }

    // epilogue: relu + masked scatter-max (non-negative floats compare as ints)
#pragma unroll
    for (int i = 0; i < 8; i++) {
        const int p = ptg * 8 + i;
        if (!smk[p]) continue;
        const int cell = sidx[p];
        int* ob = (int*)out + (((size_t)(b * 64 + chg * 8)) << 20) + cell;
#pragma unroll
        for (int j = 0; j < 4; j++) {
            float lo, hi; unpk(acc[i][j], lo, hi);
            if (lo > 0.f) atomicMax(ob + ((size_t)(2 * j) << 20),     __float_as_int(lo));
            if (hi > 0.f) atomicMax(ob + ((size_t)(2 * j + 1) << 20), __float_as_int(hi));
        }
    }
}

// ---------------------------------------------------------------------------
extern "C" void kernel_launch(void* const* d_in, const int* in_sizes, int n_in,
                              void* d_out, int out_size) {
    const float* points = (const float*)d_in[0];
    const int* pmask    = (const int*)d_in[1];
    const float* W1 = (const float*)d_in[2];
    const float* g1 = (const float*)d_in[3];
    const float* b1 = (const float*)d_in[4];
    const float* m1 = (const float*)d_in[5];
    const float* v1 = (const float*)d_in[6];
    const float* W2 = (const float*)d_in[7];
    const float* g2 = (const float*)d_in[8];
    const float* b2 = (const float*)d_in[9];
    const float* m2 = (const float*)d_in[10];
    const float* v2 = (const float*)d_in[11];
    float* out = (float*)d_out;

    cudaFuncSetAttribute(pfe_kernel, cudaFuncAttributeMaxDynamicSharedMemorySize, SMEM_BYTES);

    init_kernel<<<ZBLK, 256>>>(points, pmask, W1, g1, b1, m1, v1,
                               W2, g2, b2, m2, v2, (float4*)out);

    dim3 mg((NPTS + PPB - 1) / PPB, BATCH);
    pfe_kernel<<<mg, MTHREADS, SMEM_BYTES>>>(points, pmask, out);
}

// round 5
// speedup vs baseline: 1.2613x; 1.0227x over previous
#include <cuda_runtime.h>

#define NPTS 250000
#define BATCH 2
#define OUT_ELEMS (BATCH * 64 * 1024 * 1024)
#define NCELL (1024 * 1024)
#define ZBLK 4096
#define ZMB 64
#define PPB 128
#define MTHREADS 128
#define SMEM_BYTES 54272       // 13568 floats

typedef unsigned long long ull;

__device__ float g_part[BATCH][2][ZMB];   // zmean partials
__device__ float g_fold[4864];            // W1f|t1|W2f|t2
__device__ int   g_cnt[BATCH][NCELL];     // per-cell histogram (zeroed in init)
__device__ int   g_cursor[BATCH][NCELL];  // exclusive starts -> scatter cursors
__device__ int   g_cell[BATCH][NPTS];     // cell per point (-1 if masked out)
__device__ int   g_idx[BATCH][NPTS];      // cell-sorted point ids
__device__ int   g_bsum[BATCH][1024];
__device__ int   g_boff[BATCH][1024];
__device__ int   g_nvalid[BATCH];

__device__ __forceinline__ ull dup2(float a) {
    ull r; asm("mov.b64 %0, {%1, %1};" : "=l"(r) : "f"(a)); return r;
}
__device__ __forceinline__ ull fma2(ull a, ull b, ull c) {
    ull d; asm("fma.rn.f32x2 %0, %1, %2, %3;" : "=l"(d) : "l"(a), "l"(b), "l"(c)); return d;
}
__device__ __forceinline__ void unpk(ull v, float& lo, float& hi) {
    asm("mov.b64 {%0, %1}, %2;" : "=f"(lo), "=f"(hi) : "l"(v));
}

// exact replica of reference binning
__device__ __forceinline__ int cell_of(float x, float y) {
    const float fx = __fdiv_rn(x - (-51.2f), 0.1f);
    const float fy = __fdiv_rn(y - (-51.2f), 0.1f);
    int px = min(max((int)floorf(fx), 0), 1023);
    int py = min(max((int)floorf(fy), 0), 1023);
    return py * 1024 + px;
}

// ---------------------------------------------------------------------------
// init: zero 512MB output + histogram + BN fold
// ---------------------------------------------------------------------------
__global__ void init_kernel(const float* __restrict__ W1, const float* __restrict__ g1,
                            const float* __restrict__ b1, const float* __restrict__ m1,
                            const float* __restrict__ v1,
                            const float* __restrict__ W2, const float* __restrict__ g2,
                            const float* __restrict__ b2, const float* __restrict__ m2,
                            const float* __restrict__ v2,
                            float4* __restrict__ out4) {
    const int bid = blockIdx.x, tid = threadIdx.x;
    const float4 z4 = make_float4(0.f, 0.f, 0.f, 0.f);
    const int total4 = OUT_ELEMS / 4;
    for (int i = bid * 256 + tid; i < total4; i += ZBLK * 256) out4[i] = z4;

    int4* cnt4 = (int4*)g_cnt;
    const int4 zi4 = make_int4(0, 0, 0, 0);
    const int ctot4 = BATCH * NCELL / 4;
    for (int i = bid * 256 + tid; i < ctot4; i += ZBLK * 256) cnt4[i] = zi4;

    if (bid == ZBLK - 1 && tid < 64) {
        const int c = tid;
        const float s1 = g1[c] * rsqrtf(v1[c] + 1e-5f);
        const float s2 = g2[c] * rsqrtf(v2[c] + 1e-5f);
        g_fold[640 + c]  = b1[c] - m1[c] * s1;
        g_fold[4800 + c] = b2[c] - m2[c] * s2;
#pragma unroll
        for (int f = 0; f < 10; f++) g_fold[f * 64 + c] = W1[f * 64 + c] * s1;
        for (int k = 0; k < 64; k++) g_fold[704 + k * 64 + c] = W2[k * 64 + c] * s2;
    }
}

// ---------------------------------------------------------------------------
// bin: cell per point + histogram + zmean partials
// ---------------------------------------------------------------------------
__global__ void bin_kernel(const float* __restrict__ points,
                           const int* __restrict__ mask) {
    const int b = blockIdx.y, tid = threadIdx.x;
    float s = 0.f, c = 0.f;
    for (int i = blockIdx.x * 256 + tid; i < NPTS; i += ZMB * 256) {
        const float* pp = points + ((size_t)b * NPTS + i) * 5;
        const int cl = cell_of(pp[0], pp[1]);
        const int mk = mask[(size_t)b * NPTS + i] != 0;
        g_cell[b][i] = mk ? cl : -1;
        if (mk) {
            atomicAdd(&g_cnt[b][cl], 1);
            s += pp[2];
            c += 1.f;
        }
    }
#pragma unroll
    for (int o = 16; o; o >>= 1) {
        s += __shfl_xor_sync(0xFFFFFFFFu, s, o);
        c += __shfl_xor_sync(0xFFFFFFFFu, c, o);
    }
    __shared__ float ss[8], sc[8];
    const int w = tid >> 5, l = tid & 31;
    if (l == 0) { ss[w] = s; sc[w] = c; }
    __syncthreads();
    if (tid == 0) {
        float S = 0.f, C = 0.f;
#pragma unroll
        for (int i = 0; i < 8; i++) { S += ss[i]; C += sc[i]; }
        g_part[b][0][blockIdx.x] = S;
        g_part[b][1][blockIdx.x] = C;
    }
}

// ---------------------------------------------------------------------------
// 3-stage exclusive prefix scan over g_cnt -> g_cursor
// ---------------------------------------------------------------------------
__device__ __forceinline__ int block_excl_scan_1024(int v, int* sh, int tid, int& total) {
    sh[tid] = v;
    __syncthreads();
#pragma unroll
    for (int off = 1; off < 1024; off <<= 1) {
        int t = (tid >= off) ? sh[tid - off] : 0;
        __syncthreads();
        sh[tid] += t;
        __syncthreads();
    }
    total = sh[1023];
    return sh[tid] - v;
}

__global__ void scan1_kernel() {
    __shared__ int sh[1024];
    const int b = blockIdx.y, bx = blockIdx.x, tid = threadIdx.x;
    const int v = g_cnt[b][bx * 1024 + tid];
    int total;
    const int e = block_excl_scan_1024(v, sh, tid, total);
    g_cursor[b][bx * 1024 + tid] = e;
    if (tid == 1023) g_bsum[b][bx] = total;
}

__global__ void scan2_kernel() {
    __shared__ int sh[1024];
    const int b = blockIdx.y, tid = threadIdx.x;
    const int v = g_bsum[b][tid];
    int total;
    const int e = block_excl_scan_1024(v, sh, tid, total);
    g_boff[b][tid] = e;
    if (tid == 1023) g_nvalid[b] = total;
}

__global__ void scan3_kernel() {
    const int b = blockIdx.y, bx = blockIdx.x, tid = threadIdx.x;
    g_cursor[b][bx * 1024 + tid] += g_boff[b][bx];
}

// ---------------------------------------------------------------------------
// scatter: build cell-sorted point id list
// ---------------------------------------------------------------------------
__global__ void scatter_kernel() {
    const int b = blockIdx.y;
    for (int i = blockIdx.x * 256 + threadIdx.x; i < NPTS; i += 128 * 256) {
        const int cl = g_cell[b][i];
        if (cl >= 0) {
            const int pos = atomicAdd(&g_cursor[b][cl], 1);
            g_idx[b][pos] = i;
        }
    }
}

// ---------------------------------------------------------------------------
// Fused PFN + scatter-max over cell-sorted points.
// ---------------------------------------------------------------------------
__global__ __launch_bounds__(MTHREADS, 4)
void pfe_kernel(const float* __restrict__ points,
                float* __restrict__ out) {
    const int b = blockIdx.y;
    const int nvalid = g_nvalid[b];
    const int p0 = blockIdx.x * PPB;
    if (p0 >= nvalid) return;

    extern __shared__ __align__(16) float smem[];
    float* W1s = smem;                  // 640
    float* t1s = smem + 640;            // 64
    float* W2s = smem + 704;            // 4096
    float* t2s = smem + 4800;           // 64
    float* h1s = smem + 4864;           // 64 rows x stride 132
    int* sidx  = (int*)(smem + 13312);  // 128
    int* smk   = sidx + 128;            // 128
    __shared__ float zred;

    const int tid = threadIdx.x;

    for (int i = tid; i < 4864; i += MTHREADS) smem[i] = g_fold[i];
    if (tid < 32) {
        float s = g_part[b][0][tid] + g_part[b][0][tid + 32];
        float c = g_part[b][1][tid] + g_part[b][1][tid + 32];
#pragma unroll
        for (int o = 16; o; o >>= 1) {
            s += __shfl_xor_sync(0xFFFFFFFFu, s, o);
            c += __shfl_xor_sync(0xFFFFFFFFu, c, o);
        }
        if (tid == 0) zred = s / fmaxf(c, 1.0f);
    }
    __syncthreads();
    const float zm = zred;

    // ---------------- Phase A (gather sorted points) ----------------
    {
        const int s = p0 + tid;
        float aug[10];
        int cell = 0, valid = 0;
        if (s < nvalid) {
            const int gi = g_idx[b][s];
            const float* pp = points + ((size_t)b * NPTS + gi) * 5;
            const float x = pp[0], y = pp[1], z = pp[2];
            aug[3] = pp[3]; aug[4] = pp[4];
            const float fx = __fdiv_rn(x - (-51.2f), 0.1f);
            const float fy = __fdiv_rn(y - (-51.2f), 0.1f);
            int px = min(max((int)floorf(fx), 0), 1023);
            int py = min(max((int)floorf(fy), 0), 1023);
            const float pxf = (float)px, pyf = (float)py;
            aug[0] = x; aug[1] = y; aug[2] = z;
            aug[5] = x - (pxf * 0.1f + (-51.2f) + 0.05f);
            aug[6] = y - (pyf * 0.1f + (-51.2f) + 0.05f);
            aug[7] = z - zm;
            aug[8] = x - (pxf * 0.1f + (-51.2f));
            aug[9] = y - (pyf * 0.1f + (-51.2f));
            cell = py * 1024 + px;
            valid = 1;
        } else {
#pragma unroll
            for (int f = 0; f < 10; f++) aug[f] = 0.f;
        }
        sidx[tid] = cell;
        smk[tid] = valid;

        ull h2[32];
        const ull* t1u = (const ull*)t1s;
#pragma unroll
        for (int c2 = 0; c2 < 32; c2++) h2[c2] = t1u[c2];
        const ull* W1u = (const ull*)W1s;
#pragma unroll
        for (int f = 0; f < 10; f++) {
            const ull a = dup2(aug[f]);
#pragma unroll
            for (int c2 = 0; c2 < 32; c2++)
                h2[c2] = fma2(a, W1u[f * 32 + c2], h2[c2]);
        }
#pragma unroll
        for (int c2 = 0; c2 < 32; c2++) {
            float lo, hi; unpk(h2[c2], lo, hi);
            h1s[(2 * c2) * 132 + tid]     = fmaxf(lo, 0.f);
            h1s[(2 * c2 + 1) * 132 + tid] = fmaxf(hi, 0.f);
        }
    }
    __syncthreads();

    // ---------------- Phase B ----------------
    const int chg = tid & 7;
    const int ptg = tid >> 3;
    const float* hbase = h1s + ptg * 8;
    const ull* W2u = (const ull*)W2s;
    const ull* t2u = (const ull*)t2s;

    ull acc[8][4];
    {
        const ull t0 = t2u[chg * 4 + 0], t1v = t2u[chg * 4 + 1];
        const ull t2v = t2u[chg * 4 + 2], t3v = t2u[chg * 4 + 3];
#pragma unroll
        for (int i = 0; i < 8; i++) {
            acc[i][0] = t0; acc[i][1] = t1v; acc[i][2] = t2v; acc[i][3] = t3v;
        }
    }

#pragma unroll 4
    for (int k = 0; k < 64; k++) {
        const float4 ha = *(const float4*)(hbase + k * 132);
        const float4 hb = *(const float4*)(hbase + k * 132 + 4);
        const ull w0 = W2u[k * 32 + chg * 4 + 0];
        const ull w1 = W2u[k * 32 + chg * 4 + 1];
        const ull w2 = W2u[k * 32 + chg * 4 + 2];
        const ull w3 = W2u[k * 32 + chg * 4 + 3];
        const ull hd[8] = {dup2(ha.x), dup2(ha.y), dup2(ha.z), dup2(ha.w),
                           dup2(hb.x), dup2(hb.y), dup2(hb.z), dup2(hb.w)};
#pragma unroll
        for (int i = 0; i < 8; i++) {
            acc[i][0] = fma2(hd[i], w0, acc[i][0]);
            acc[i][1] = fma2(hd[i], w1, acc[i][1]);
            acc[i][2] = fma2(hd[i], w2, acc[i][2]);
            acc[i][3] = fma2(hd[i], w3, acc[i][3]);
        }
    }

    // ---------------- epilogue: run-length dedup + scatter-max ----------------
    int* obase = (int*)out + (((size_t)(b * 64 + chg * 8)) << 20);
    const int base = ptg * 8;

    float rm[8];
#pragma unroll
    for (int j = 0; j < 4; j++) unpk(acc[0][j], rm[2 * j], rm[2 * j + 1]);
    int cur = sidx[base];
    int curv = smk[base];

#pragma unroll
    for (int i = 1; i < 8; i++) {
        const int v = smk[base + i];
        const int cl = sidx[base + i];
        float f[8];
#pragma unroll
        for (int j = 0; j < 4; j++) unpk(acc[i][j], f[2 * j], f[2 * j + 1]);
        if (v && cl == cur) {
#pragma unroll
            for (int t = 0; t < 8; t++) rm[t] = fmaxf(rm[t], f[t]);
        } else {
            if (curv) {
                int* ob = obase + cur;
#pragma unroll
                for (int t = 0; t < 8; t++)
                    if (rm[t] > 0.f) atomicMax(ob + ((size_t)t << 20), __float_as_int(rm[t]));
            }
#pragma unroll
            for (int t = 0; t < 8; t++) rm[t] = f[t];
            cur = cl;
            curv = v;
        }
    }
    if (curv) {
        int* ob = obase + cur;
#pragma unroll
        for (int t = 0; t < 8; t++)
            if (rm[t] > 0.f) atomicMax(ob + ((size_t)t << 20), __float_as_int(rm[t]));
    }
}

// ---------------------------------------------------------------------------
extern "C" void kernel_launch(void* const* d_in, const int* in_sizes, int n_in,
                              void* d_out, int out_size) {
    const float* points = (const float*)d_in[0];
    const int* pmask    = (const int*)d_in[1];
    const float* W1 = (const float*)d_in[2];
    const float* g1 = (const float*)d_in[3];
    const float* b1 = (const float*)d_in[4];
    const float* m1 = (const float*)d_in[5];
    const float* v1 = (const float*)d_in[6];
    const float* W2 = (const float*)d_in[7];
    const float* g2 = (const float*)d_in[8];
    const float* b2 = (const float*)d_in[9];
    const float* m2 = (const float*)d_in[10];
    const float* v2 = (const float*)d_in[11];
    float* out = (float*)d_out;

    cudaFuncSetAttribute(pfe_kernel, cudaFuncAttributeMaxDynamicSharedMemorySize, SMEM_BYTES);

    init_kernel<<<ZBLK, 256>>>(W1, g1, b1, m1, v1, W2, g2, b2, m2, v2, (float4*)out);

    dim3 bg(ZMB, BATCH);
    bin_kernel<<<bg, 256>>>(points, pmask);

    dim3 s1g(1024, BATCH);
    scan1_kernel<<<s1g, 1024>>>();
    dim3 s2g(1, BATCH);
    scan2_kernel<<<s2g, 1024>>>();
    scan3_kernel<<<s1g, 1024>>>();

    dim3 scg(128, BATCH);
    scatter_kernel<<<scg, 256>>>();

    dim3 mg((NPTS + PPB - 1) / PPB, BATCH);
    pfe_kernel<<<mg, MTHREADS, SMEM_BYTES>>>(points, out);
}

// round 6
// speedup vs baseline: 1.5210x; 1.2059x over previous
#include <cuda_runtime.h>

#define NPTS 250000
#define BATCH 2
#define OUT_ELEMS (BATCH * 64 * 1024 * 1024)
#define NCELL (1024 * 1024)
#define NCHUNK 2048            // fill chunks of 512 cells
#define ZMB 64
#define PPB 128
#define MTHREADS 128
#define NTILE ((NPTS + PPB - 1) / PPB)   // 1954
#define SMEM_BYTES 54272       // 13568 floats

typedef unsigned long long ull;

__device__ float g_part[BATCH][2][ZMB];   // zmean partials
__device__ float g_fold[4864];            // W1f|t1|W2f|t2
__device__ int   g_cnt[BATCH][NCELL];     // per-cell histogram
__device__ int   g_cursor[BATCH][NCELL];  // chunk-local exclusive prefixes -> cursors
__device__ int   g_cell[BATCH][NPTS];     // cell per point (-1 if masked out)
__device__ int   g_idx[BATCH][NPTS];      // cell-sorted point ids
__device__ int   g_bsum[BATCH][256];
__device__ int   g_boff[BATCH][256];
__device__ int   g_nvalid[BATCH];

__device__ __forceinline__ ull dup2(float a) {
    ull r; asm("mov.b64 %0, {%1, %1};" : "=l"(r) : "f"(a)); return r;
}
__device__ __forceinline__ ull fma2(ull a, ull b, ull c) {
    ull d; asm("fma.rn.f32x2 %0, %1, %2, %3;" : "=l"(d) : "l"(a), "l"(b), "l"(c)); return d;
}
__device__ __forceinline__ void unpk(ull v, float& lo, float& hi) {
    asm("mov.b64 {%0, %1}, %2;" : "=f"(lo), "=f"(hi) : "l"(v));
}

// exact replica of reference binning
__device__ __forceinline__ int cell_of(float x, float y) {
    const float fx = __fdiv_rn(x - (-51.2f), 0.1f);
    const float fy = __fdiv_rn(y - (-51.2f), 0.1f);
    int px = min(max((int)floorf(fx), 0), 1023);
    int py = min(max((int)floorf(fy), 0), 1023);
    return py * 1024 + px;
}

// ---------------------------------------------------------------------------
// zero g_cnt (8MB) + BN fold
// ---------------------------------------------------------------------------
__global__ void zcnt_kernel(const float* __restrict__ W1, const float* __restrict__ g1,
                            const float* __restrict__ b1, const float* __restrict__ m1,
                            const float* __restrict__ v1,
                            const float* __restrict__ W2, const float* __restrict__ g2,
                            const float* __restrict__ b2, const float* __restrict__ m2,
                            const float* __restrict__ v2) {
    const int bid = blockIdx.x, tid = threadIdx.x;
    int4* cnt4 = (int4*)g_cnt;
    const int4 zi4 = make_int4(0, 0, 0, 0);
    const int ctot4 = BATCH * NCELL / 4;
    for (int i = bid * 256 + tid; i < ctot4; i += 512 * 256) cnt4[i] = zi4;

    if (bid == 0 && tid < 64) {
        const int c = tid;
        const float s1 = g1[c] * rsqrtf(v1[c] + 1e-5f);
        const float s2 = g2[c] * rsqrtf(v2[c] + 1e-5f);
        g_fold[640 + c]  = b1[c] - m1[c] * s1;
        g_fold[4800 + c] = b2[c] - m2[c] * s2;
#pragma unroll
        for (int f = 0; f < 10; f++) g_fold[f * 64 + c] = W1[f * 64 + c] * s1;
        for (int k = 0; k < 64; k++) g_fold[704 + k * 64 + c] = W2[k * 64 + c] * s2;
    }
}

// ---------------------------------------------------------------------------
// bin: cell per point + histogram + zmean partials
// ---------------------------------------------------------------------------
__global__ void bin_kernel(const float* __restrict__ points,
                           const int* __restrict__ mask) {
    const int b = blockIdx.y, tid = threadIdx.x;
    float s = 0.f, c = 0.f;
    for (int i = blockIdx.x * 256 + tid; i < NPTS; i += ZMB * 256) {
        const float* pp = points + ((size_t)b * NPTS + i) * 5;
        const int cl = cell_of(pp[0], pp[1]);
        const int mk = mask[(size_t)b * NPTS + i] != 0;
        g_cell[b][i] = mk ? cl : -1;
        if (mk) {
            atomicAdd(&g_cnt[b][cl], 1);
            s += pp[2];
            c += 1.f;
        }
    }
#pragma unroll
    for (int o = 16; o; o >>= 1) {
        s += __shfl_xor_sync(0xFFFFFFFFu, s, o);
        c += __shfl_xor_sync(0xFFFFFFFFu, c, o);
    }
    __shared__ float ss[8], sc[8];
    const int w = tid >> 5, l = tid & 31;
    if (l == 0) { ss[w] = s; sc[w] = c; }
    __syncthreads();
    if (tid == 0) {
        float S = 0.f, C = 0.f;
#pragma unroll
        for (int i = 0; i < 8; i++) { S += ss[i]; C += sc[i]; }
        g_part[b][0][blockIdx.x] = S;
        g_part[b][1][blockIdx.x] = C;
    }
}

// ---------------------------------------------------------------------------
// scan1: per-4096-cell-chunk exclusive scan (warp-shuffle), 4 cells/thread
// ---------------------------------------------------------------------------
__global__ void scan1_kernel() {
    const int b = blockIdx.y, bx = blockIdx.x, tid = threadIdx.x;
    const int base = bx * 4096 + tid * 4;
    const int4 v = *(const int4*)&g_cnt[b][base];
    const int tsum = v.x + v.y + v.z + v.w;
    int s = tsum;
    const int lane = tid & 31, wid = tid >> 5;
#pragma unroll
    for (int o = 1; o < 32; o <<= 1) {
        int t = __shfl_up_sync(0xFFFFFFFFu, s, o);
        if (lane >= o) s += t;
    }
    __shared__ int wsum[32];
    if (lane == 31) wsum[wid] = s;
    __syncthreads();
    if (wid == 0) {
        int w = wsum[lane];
#pragma unroll
        for (int o = 1; o < 32; o <<= 1) {
            int t = __shfl_up_sync(0xFFFFFFFFu, w, o);
            if (lane >= o) w += t;
        }
        wsum[lane] = w;
    }
    __syncthreads();
    const int wbase = wid ? wsum[wid - 1] : 0;
    const int excl = wbase + s - tsum;
    int4 e;
    e.x = excl; e.y = e.x + v.x; e.z = e.y + v.y; e.w = e.z + v.z;
    *(int4*)&g_cursor[b][base] = e;
    if (tid == 1023) g_bsum[b][bx] = e.w + v.w;
}

// ---------------------------------------------------------------------------
// scan2: exclusive scan of 256 chunk sums per batch
// ---------------------------------------------------------------------------
__global__ void scan2_kernel() {
    const int b = blockIdx.y, tid = threadIdx.x;
    const int v = g_bsum[b][tid];
    int s = v;
    const int lane = tid & 31, wid = tid >> 5;
#pragma unroll
    for (int o = 1; o < 32; o <<= 1) {
        int t = __shfl_up_sync(0xFFFFFFFFu, s, o);
        if (lane >= o) s += t;
    }
    __shared__ int wsum[8];
    if (lane == 31) wsum[wid] = s;
    __syncthreads();
    if (wid == 0 && lane < 8) {
        int w = wsum[lane];
#pragma unroll
        for (int o = 1; o < 8; o <<= 1) {
            int t = __shfl_up_sync(0xFFu, w, o);
            if (lane >= o) w += t;
        }
        wsum[lane] = w;
    }
    __syncthreads();
    const int excl = (wid ? wsum[wid - 1] : 0) + s - v;
    g_boff[b][tid] = excl;
    if (tid == 255) g_nvalid[b] = excl + v;
}

// ---------------------------------------------------------------------------
// scatter: build cell-sorted point id list (chunk offset added on the fly)
// ---------------------------------------------------------------------------
__global__ void scatter_kernel() {
    const int b = blockIdx.y;
    for (int i = blockIdx.x * 256 + threadIdx.x; i < NPTS; i += 128 * 256) {
        const int cl = g_cell[b][i];
        if (cl >= 0) {
            const int pos = atomicAdd(&g_cursor[b][cl], 1) + g_boff[b][cl >> 12];
            g_idx[b][pos] = i;
        }
    }
}

// ---------------------------------------------------------------------------
// Fused fill + PFN + scatter-max.
// Fill: zero 512MB output. Inactive cells: plain st.128 (pfe never touches
// them). Active cells: RED.MAX(addr,0) — commutes with pfe's scatter-max,
// so NO ordering between fill and compute is needed. This overlaps the
// DRAM-bound fill with the issue-bound GEMM across co-resident blocks.
// ---------------------------------------------------------------------------
__global__ __launch_bounds__(MTHREADS, 4)
void pfe_kernel(const float* __restrict__ points,
                float* __restrict__ out) {
    const int tid = threadIdx.x;
    const int b = blockIdx.y;

    // ---------------- fill phase ----------------
    for (int chunk = blockIdx.x; chunk < NCHUNK; chunk += NTILE) {
        const int cbase = chunk * 512 + tid * 4;
        const int4 cnt = *(const int4*)&g_cnt[b][cbase];
        int* dst0 = (int*)out + (((size_t)(b * 64)) << 20) + cbase;
        if ((cnt.x | cnt.y | cnt.z | cnt.w) == 0) {
            const int4 z = make_int4(0, 0, 0, 0);
#pragma unroll 8
            for (int c = 0; c < 64; c++)
                *(int4*)(dst0 + ((size_t)c << 20)) = z;
        } else {
#pragma unroll 4
            for (int c = 0; c < 64; c++) {
                int* d = dst0 + ((size_t)c << 20);
                if (cnt.x) atomicMax(d + 0, 0); else d[0] = 0;
                if (cnt.y) atomicMax(d + 1, 0); else d[1] = 0;
                if (cnt.z) atomicMax(d + 2, 0); else d[2] = 0;
                if (cnt.w) atomicMax(d + 3, 0); else d[3] = 0;
            }
        }
    }

    // ---------------- compute phase ----------------
    const int nvalid = g_nvalid[b];
    const int p0 = blockIdx.x * PPB;
    if (p0 >= nvalid) return;

    extern __shared__ __align__(16) float smem[];
    float* W1s = smem;                  // 640
    float* t1s = smem + 640;            // 64
    float* W2s = smem + 704;            // 4096
    float* t2s = smem + 4800;           // 64
    float* h1s = smem + 4864;           // 64 rows x stride 132
    int* sidx  = (int*)(smem + 13312);  // 128
    int* smk   = sidx + 128;            // 128
    __shared__ float zred;

    for (int i = tid; i < 4864; i += MTHREADS) smem[i] = g_fold[i];
    if (tid < 32) {
        float s = g_part[b][0][tid] + g_part[b][0][tid + 32];
        float c = g_part[b][1][tid] + g_part[b][1][tid + 32];
#pragma unroll
        for (int o = 16; o; o >>= 1) {
            s += __shfl_xor_sync(0xFFFFFFFFu, s, o);
            c += __shfl_xor_sync(0xFFFFFFFFu, c, o);
        }
        if (tid == 0) zred = s / fmaxf(c, 1.0f);
    }
    __syncthreads();
    const float zm = zred;

    // ---------------- Phase A (gather sorted points) ----------------
    {
        const int s = p0 + tid;
        float aug[10];
        int cell = 0, valid = 0;
        if (s < nvalid) {
            const int gi = g_idx[b][s];
            const float* pp = points + ((size_t)b * NPTS + gi) * 5;
            const float x = pp[0], y = pp[1], z = pp[2];
            aug[3] = pp[3]; aug[4] = pp[4];
            const float fx = __fdiv_rn(x - (-51.2f), 0.1f);
            const float fy = __fdiv_rn(y - (-51.2f), 0.1f);
            int px = min(max((int)floorf(fx), 0), 1023);
            int py = min(max((int)floorf(fy), 0), 1023);
            const float pxf = (float)px, pyf = (float)py;
            aug[0] = x; aug[1] = y; aug[2] = z;
            aug[5] = x - (pxf * 0.1f + (-51.2f) + 0.05f);
            aug[6] = y - (pyf * 0.1f + (-51.2f) + 0.05f);
            aug[7] = z - zm;
            aug[8] = x - (pxf * 0.1f + (-51.2f));
            aug[9] = y - (pyf * 0.1f + (-51.2f));
            cell = py * 1024 + px;
            valid = 1;
        } else {
#pragma unroll
            for (int f = 0; f < 10; f++) aug[f] = 0.f;
        }
        sidx[tid] = cell;
        smk[tid] = valid;

        ull h2[32];
        const ull* t1u = (const ull*)t1s;
#pragma unroll
        for (int c2 = 0; c2 < 32; c2++) h2[c2] = t1u[c2];
        const ull* W1u = (const ull*)W1s;
#pragma unroll
        for (int f = 0; f < 10; f++) {
            const ull a = dup2(aug[f]);
#pragma unroll
            for (int c2 = 0; c2 < 32; c2++)
                h2[c2] = fma2(a, W1u[f * 32 + c2], h2[c2]);
        }
#pragma unroll
        for (int c2 = 0; c2 < 32; c2++) {
            float lo, hi; unpk(h2[c2], lo, hi);
            h1s[(2 * c2) * 132 + tid]     = fmaxf(lo, 0.f);
            h1s[(2 * c2 + 1) * 132 + tid] = fmaxf(hi, 0.f);
        }
    }
    __syncthreads();

    // ---------------- Phase B ----------------
    const int chg = tid & 7;
    const int ptg = tid >> 3;
    const float* hbase = h1s + ptg * 8;
    const ull* W2u = (const ull*)W2s;
    const ull* t2u = (const ull*)t2s;

    ull acc[8][4];
    {
        const ull t0 = t2u[chg * 4 + 0], t1v = t2u[chg * 4 + 1];
        const ull t2v = t2u[chg * 4 + 2], t3v = t2u[chg * 4 + 3];
#pragma unroll
        for (int i = 0; i < 8; i++) {
            acc[i][0] = t0; acc[i][1] = t1v; acc[i][2] = t2v; acc[i][3] = t3v;
        }
    }

#pragma unroll 4
    for (int k = 0; k < 64; k++) {
        const float4 ha = *(const float4*)(hbase + k * 132);
        const float4 hb = *(const float4*)(hbase + k * 132 + 4);
        const ull w0 = W2u[k * 32 + chg * 4 + 0];
        const ull w1 = W2u[k * 32 + chg * 4 + 1];
        const ull w2 = W2u[k * 32 + chg * 4 + 2];
        const ull w3 = W2u[k * 32 + chg * 4 + 3];
        const ull hd[8] = {dup2(ha.x), dup2(ha.y), dup2(ha.z), dup2(ha.w),
                           dup2(hb.x), dup2(hb.y), dup2(hb.z), dup2(hb.w)};
#pragma unroll
        for (int i = 0; i < 8; i++) {
            acc[i][0] = fma2(hd[i], w0, acc[i][0]);
            acc[i][1] = fma2(hd[i], w1, acc[i][1]);
            acc[i][2] = fma2(hd[i], w2, acc[i][2]);
            acc[i][3] = fma2(hd[i], w3, acc[i][3]);
        }
    }

    // ---------------- epilogue: run-length dedup + scatter-max ----------------
    int* obase = (int*)out + (((size_t)(b * 64 + chg * 8)) << 20);
    const int base = ptg * 8;

    float rm[8];
#pragma unroll
    for (int j = 0; j < 4; j++) unpk(acc[0][j], rm[2 * j], rm[2 * j + 1]);
    int cur = sidx[base];
    int curv = smk[base];

#pragma unroll
    for (int i = 1; i < 8; i++) {
        const int v = smk[base + i];
        const int cl = sidx[base + i];
        float f[8];
#pragma unroll
        for (int j = 0; j < 4; j++) unpk(acc[i][j], f[2 * j], f[2 * j + 1]);
        if (v && cl == cur) {
#pragma unroll
            for (int t = 0; t < 8; t++) rm[t] = fmaxf(rm[t], f[t]);
        } else {
            if (curv) {
                int* ob = obase + cur;
#pragma unroll
                for (int t = 0; t < 8; t++)
                    if (rm[t] > 0.f) atomicMax(ob + ((size_t)t << 20), __float_as_int(rm[t]));
            }
#pragma unroll
            for (int t = 0; t < 8; t++) rm[t] = f[t];
            cur = cl;
            curv = v;
        }
    }
    if (curv) {
        int* ob = obase + cur;
#pragma unroll
        for (int t = 0; t < 8; t++)
            if (rm[t] > 0.f) atomicMax(ob + ((size_t)t << 20), __float_as_int(rm[t]));
    }
}

// ---------------------------------------------------------------------------
extern "C" void kernel_launch(void* const* d_in, const int* in_sizes, int n_in,
                              void* d_out, int out_size) {
    const float* points = (const float*)d_in[0];
    const int* pmask    = (const int*)d_in[1];
    const float* W1 = (const float*)d_in[2];
    const float* g1 = (const float*)d_in[3];
    const float* b1 = (const float*)d_in[4];
    const float* m1 = (const float*)d_in[5];
    const float* v1 = (const float*)d_in[6];
    const float* W2 = (const float*)d_in[7];
    const float* g2 = (const float*)d_in[8];
    const float* b2 = (const float*)d_in[9];
    const float* m2 = (const float*)d_in[10];
    const float* v2 = (const float*)d_in[11];
    float* out = (float*)d_out;

    cudaFuncSetAttribute(pfe_kernel, cudaFuncAttributeMaxDynamicSharedMemorySize, SMEM_BYTES);

    zcnt_kernel<<<512, 256>>>(W1, g1, b1, m1, v1, W2, g2, b2, m2, v2);

    dim3 bg(ZMB, BATCH);
    bin_kernel<<<bg, 256>>>(points, pmask);

    dim3 s1g(256, BATCH);
    scan1_kernel<<<s1g, 1024>>>();
    dim3 s2g(1, BATCH);
    scan2_kernel<<<s2g, 256>>>();

    dim3 scg(128, BATCH);
    scatter_kernel<<<scg, 256>>>();

    dim3 mg(NTILE, BATCH);
    pfe_kernel<<<mg, MTHREADS, SMEM_BYTES>>>(points, out);
}